// round 8
// baseline (speedup 1.0000x reference)
#include <cuda_runtime.h>
#include <cstdint>

#define MAXN 40000
#define MAXE 1048576
#define FDIM 128
#define SCAN_BLK 1024
#define MAX_PART 64
#define TM 64
#define WPITCH 132

// Static scratch (no allocation allowed)
__device__ unsigned long long g_pack[MAXN];  // deg<<40 | sumw*2^20
__device__ float g_scales [2 * MAXN];        // [0,N): sm   [N,2N): sh
__device__ int   g_off    [MAXN + 1];
__device__ int   g_cursor [MAXN];
__device__ int   g_part   [MAX_PART];
__device__ int   g_partoff[MAX_PART];
__device__ int2  g_epack  [MAXE];            // .x = src, .y = float bits of w
__device__ float g_h1 [MAXN * FDIM];
__device__ float g_h2 [MAXN * FDIM];

// ---------------------------------------------------------------------------
// deg and sumw in ONE 64-bit atomic: +(1<<40) + round(w * 2^20)
__global__ void edge_stats_kernel(const int* __restrict__ dst,
                                  const float* __restrict__ w, int E) {
    int e = blockIdx.x * blockDim.x + threadIdx.x;
    if (e >= E) return;
    unsigned long long add =
        (1ULL << 40) | (unsigned long long)__float2uint_rn(w[e] * 1048576.f);
    atomicAdd(&g_pack[dst[e]], add);
}

__global__ void __launch_bounds__(SCAN_BLK)
scan_partial_kernel(int n) {
    __shared__ int sh[SCAN_BLK];
    int tid = threadIdx.x;
    int i = blockIdx.x * SCAN_BLK + tid;
    sh[tid] = (i < n) ? (int)(g_pack[i] >> 40) : 0;
    __syncthreads();
    for (int d = SCAN_BLK / 2; d > 0; d >>= 1) {
        if (tid < d) sh[tid] += sh[tid + d];
        __syncthreads();
    }
    if (tid == 0) g_part[blockIdx.x] = sh[0];
}

__global__ void scan_top_kernel(int nb, int n) {
    __shared__ int sh[MAX_PART];
    int tid = threadIdx.x;
    int v = (tid < nb) ? g_part[tid] : 0;
    sh[tid] = v;
    __syncthreads();
    for (int d = 1; d < MAX_PART; d <<= 1) {
        int t = (tid >= d) ? sh[tid - d] : 0;
        __syncthreads();
        sh[tid] += t;
        __syncthreads();
    }
    if (tid < nb) g_partoff[tid] = sh[tid] - v;
    if (tid == 0) g_off[n] = sh[nb - 1];
}

__global__ void __launch_bounds__(SCAN_BLK)
scan_emit_kernel(int n) {
    __shared__ int sh[SCAN_BLK];
    int tid = threadIdx.x;
    int i = blockIdx.x * SCAN_BLK + tid;
    unsigned long long pk = (i < n) ? g_pack[i] : 0ULL;
    int dg = (int)(pk >> 40);
    sh[tid] = dg;
    __syncthreads();
    for (int d = 1; d < SCAN_BLK; d <<= 1) {
        int t = (tid >= d) ? sh[tid - d] : 0;
        __syncthreads();
        sh[tid] += t;
        __syncthreads();
    }
    if (i < n) {
        int ex = sh[tid] - dg + g_partoff[blockIdx.x];
        g_off[i]    = ex;
        g_cursor[i] = ex;
        float sw = (float)(pk & ((1ULL << 40) - 1ULL)) * (1.0f / 1048576.f);
        float dgf = (float)dg;
        float smv = 0.f, shv = 0.f;
        if (dg > 0) {
            float inv = 1.0f / (dgf + 1.0f);
            shv = inv;
            float swp = (sw == 0.f) ? 1.f : sw;
            smv = dgf * inv / swp;
        }
        g_scales[i]     = smv;
        g_scales[n + i] = shv;
    }
}

__global__ void scatter_kernel(const int* __restrict__ src,
                               const int* __restrict__ dst,
                               const float* __restrict__ w, int E) {
    int e = blockIdx.x * blockDim.x + threadIdx.x;
    if (e >= E) return;
    int d = dst[e];
    int pos = atomicAdd(&g_cursor[d], 1);
    g_epack[pos] = make_int2(src[e], __float_as_int(w[e]));
}

// ---------------------------------------------------------------------------
// Fused layer: per 64-node tile, (1) warps CSR-aggregate into smem Xs,
// (2) 8-node register-blocked FFMA GEMM + relu.
// Two co-resident blocks/SM interleave gather stalls with FFMA issue.
__global__ void __launch_bounds__(256, 2)
fused_layer_kernel(const float4* __restrict__ h,
                   const float* __restrict__ W,     // [128,128] [o][k]
                   const float* __restrict__ bias,
                   float* __restrict__ hout, int n) {
    extern __shared__ float smem[];
    float* Ws = smem;                 // 128 * 132
    float* Xs = smem + FDIM * WPITCH; // 64 * 128
    int tid = threadIdx.x;
    int lane = tid & 31;
    int wp   = tid >> 5;
    const unsigned FULL = 0xffffffffu;
    int l8 = lane & 7;

    // Load W transposed (once per block)
    for (int i = tid; i < FDIM * FDIM; i += 256) {
        int o = i >> 7, k = i & 127;
        Ws[k * WPITCH + o] = W[i];
    }
    float4 bv = *reinterpret_cast<const float4*>(&bias[lane * 4]);

    int ntiles = (n + TM - 1) / TM;
    for (int tile = blockIdx.x; tile < ntiles; tile += gridDim.x) {
        __syncthreads();  // Ws ready / previous tile's GEMM reads done
        int n0 = tile * TM;

        // ---- Aggregation phase: warp wp fills Xs rows [8wp, 8wp+8) ----
        for (int j = 0; j < 8; j++) {
            int nl = (wp << 3) + j;
            int node = n0 + nl;
            if (node >= n) break;
            int start = g_off[node];
            int end   = g_off[node + 1];
            float4 acc = make_float4(0.f, 0.f, 0.f, 0.f);
            int idx0 = start + l8;
            int2 p = (idx0 < end) ? g_epack[idx0] : make_int2(0, 0);
            for (int base = start; base < end; base += 8) {
                int2 cur = p;
                int nidx = base + 8 + l8;
                p = (nidx < end) ? g_epack[nidx] : make_int2(0, 0);
                int   ss[8];
                float ww[8];
#pragma unroll
                for (int q = 0; q < 8; q++) {
                    ss[q] = __shfl_sync(FULL, cur.x, q);
                    ww[q] = __int_as_float(__shfl_sync(FULL, cur.y, q));
                }
                float4 v[8];
#pragma unroll
                for (int q = 0; q < 8; q++)
                    v[q] = (base + q < end) ? h[ss[q] * 32 + lane]
                                            : make_float4(0.f, 0.f, 0.f, 0.f);
#pragma unroll
                for (int q = 0; q < 8; q++) {
                    acc.x = fmaf(v[q].x, ww[q], acc.x);
                    acc.y = fmaf(v[q].y, ww[q], acc.y);
                    acc.z = fmaf(v[q].z, ww[q], acc.z);
                    acc.w = fmaf(v[q].w, ww[q], acc.w);
                }
            }
            float sm = g_scales[node];
            float sh = g_scales[n + node];
            float4 self = h[node * 32 + lane];
            float4 o;
            o.x = fmaf(sm, acc.x, sh * self.x);
            o.y = fmaf(sm, acc.y, sh * self.y);
            o.z = fmaf(sm, acc.z, sh * self.z);
            o.w = fmaf(sm, acc.w, sh * self.w);
            *reinterpret_cast<float4*>(&Xs[nl * FDIM + lane * 4]) = o;
        }
        __syncthreads();

        // ---- GEMM phase: warp wp computes its own 8 rows x 128 outs ----
        float acc[8][4];
#pragma unroll
        for (int j = 0; j < 8; j++) {
            acc[j][0] = bv.x; acc[j][1] = bv.y;
            acc[j][2] = bv.z; acc[j][3] = bv.w;
        }
#pragma unroll 2
        for (int k = 0; k < FDIM; k++) {
            float4 wv = *reinterpret_cast<const float4*>(&Ws[k * WPITCH + lane * 4]);
#pragma unroll
            for (int j = 0; j < 8; j++) {
                float xv = Xs[((wp << 3) + j) * FDIM + k];
                acc[j][0] = fmaf(xv, wv.x, acc[j][0]);
                acc[j][1] = fmaf(xv, wv.y, acc[j][1]);
                acc[j][2] = fmaf(xv, wv.z, acc[j][2]);
                acc[j][3] = fmaf(xv, wv.w, acc[j][3]);
            }
        }
#pragma unroll
        for (int j = 0; j < 8; j++) {
            int node = n0 + (wp << 3) + j;
            if (node < n) {
                float4 r;
                r.x = fmaxf(acc[j][0], 0.f);
                r.y = fmaxf(acc[j][1], 0.f);
                r.z = fmaxf(acc[j][2], 0.f);
                r.w = fmaxf(acc[j][3], 0.f);
                *reinterpret_cast<float4*>(&hout[node * FDIM + lane * 4]) = r;
            }
        }
    }
}

// Final classifier: out = h2 @ Wo^T + bo
__global__ void __launch_bounds__(256)
out_kernel(const float4* __restrict__ h2,
           const float* __restrict__ Wo, const float* __restrict__ bo,
           float* __restrict__ out, int n) {
    __shared__ float Wos[FDIM * 32];
    int tid = threadIdx.x;
    for (int i = tid; i < 32 * FDIM; i += 256) {
        int o = i >> 7, k = i & 127;
        Wos[k * 32 + o] = Wo[i];
    }
    __syncthreads();

    int lane = tid & 31;
    int wp   = tid >> 5;
    float bias = bo[lane];
    for (int node = blockIdx.x * 8 + wp; node < n; node += gridDim.x * 8) {
        float4 x = h2[node * 32 + lane];
        float acc = bias;
#pragma unroll
        for (int j = 0; j < 32; j++) {
            float a = __shfl_sync(0xffffffffu, x.x, j);
            float b = __shfl_sync(0xffffffffu, x.y, j);
            float c = __shfl_sync(0xffffffffu, x.z, j);
            float d = __shfl_sync(0xffffffffu, x.w, j);
            int k = j << 2;
            acc += a * Wos[(k + 0) * 32 + lane];
            acc += b * Wos[(k + 1) * 32 + lane];
            acc += c * Wos[(k + 2) * 32 + lane];
            acc += d * Wos[(k + 3) * 32 + lane];
        }
        out[node * 32 + lane] = acc;
    }
}

// ---------------------------------------------------------------------------
extern "C" void kernel_launch(void* const* d_in, const int* in_sizes, int n_in,
                              void* d_out, int out_size) {
    const float* features = (const float*)d_in[0];
    const int*   src      = (const int*)  d_in[1];
    const int*   dst      = (const int*)  d_in[2];
    const float* weight   = (const float*)d_in[3];
    const float* W1       = (const float*)d_in[4];
    const float* b1       = (const float*)d_in[5];
    const float* W2       = (const float*)d_in[6];
    const float* b2       = (const float*)d_in[7];
    const float* Wo       = (const float*)d_in[8];
    const float* bo       = (const float*)d_in[9];
    float* out = (float*)d_out;

    int N = in_sizes[0] / FDIM;
    int E = in_sizes[1];

    void *ph1_v, *ph2_v, *ppack_v;
    cudaGetSymbolAddress(&ph1_v, g_h1);
    cudaGetSymbolAddress(&ph2_v, g_h2);
    cudaGetSymbolAddress(&ppack_v, g_pack);
    float* ph1 = (float*)ph1_v;
    float* ph2 = (float*)ph2_v;

    const int smem_bytes = (FDIM * WPITCH + TM * FDIM) * (int)sizeof(float); // 100352
    cudaFuncSetAttribute(fused_layer_kernel,
                         cudaFuncAttributeMaxDynamicSharedMemorySize, smem_bytes);

    int nb = (N + SCAN_BLK - 1) / SCAN_BLK;

    // CSR build (shared by both layers)
    cudaMemsetAsync(ppack_v, 0, N * sizeof(unsigned long long));
    edge_stats_kernel<<<(E + 255) / 256, 256>>>(dst, weight, E);
    scan_partial_kernel<<<nb, SCAN_BLK>>>(N);
    scan_top_kernel<<<1, MAX_PART>>>(nb, N);
    scan_emit_kernel<<<nb, SCAN_BLK>>>(N);
    scatter_kernel<<<(E + 255) / 256, 256>>>(src, dst, weight, E);

    // Layer 1 (fused agg+update)
    fused_layer_kernel<<<296, 256, smem_bytes>>>((const float4*)features, W1, b1, ph1, N);
    // Layer 2
    fused_layer_kernel<<<296, 256, smem_bytes>>>((const float4*)ph1, W2, b2, ph2, N);
    // Classifier
    out_kernel<<<2048, 256>>>((const float4*)ph2, Wo, bo, out, N);
}

// round 10
// speedup vs baseline: 1.0191x; 1.0191x over previous
#include <cuda_runtime.h>
#include <cuda_fp16.h>
#include <cstdint>

#define MAXN 40000
#define MAXE 1048576
#define FDIM 128
#define SCAN_BLK 1024
#define MAX_PART 64
#define TM 64
#define WPITCH 132

// Static scratch (no allocation allowed)
__device__ unsigned long long g_pack[MAXN];  // deg<<40 | sumw*2^20
__device__ float g_scales [2 * MAXN];        // [0,N): sm   [N,2N): sh
__device__ int   g_off    [MAXN + 1];
__device__ int   g_cursor [MAXN];
__device__ int   g_part   [MAX_PART];
__device__ int   g_partoff[MAX_PART];
__device__ int2  g_epack  [MAXE];            // .x = src, .y = float bits of w
__device__ float g_X  [MAXN * FDIM];
__device__ float g_h1 [MAXN * FDIM];
__device__ float g_h2 [MAXN * FDIM];
__device__ uint2 g_hf16[MAXN * (FDIM / 4)];  // fp16 copy of gather table

// ---------------------------------------------------------------------------
// deg and sumw in ONE 64-bit atomic: +(1<<40) + round(w * 2^20)
__global__ void edge_stats_kernel(const int* __restrict__ dst,
                                  const float* __restrict__ w, int E) {
    int e = blockIdx.x * blockDim.x + threadIdx.x;
    if (e >= E) return;
    unsigned long long add =
        (1ULL << 40) | (unsigned long long)__float2uint_rn(w[e] * 1048576.f);
    atomicAdd(&g_pack[dst[e]], add);
}

__global__ void __launch_bounds__(SCAN_BLK)
scan_partial_kernel(int n) {
    __shared__ int sh[SCAN_BLK];
    int tid = threadIdx.x;
    int i = blockIdx.x * SCAN_BLK + tid;
    sh[tid] = (i < n) ? (int)(g_pack[i] >> 40) : 0;
    __syncthreads();
    for (int d = SCAN_BLK / 2; d > 0; d >>= 1) {
        if (tid < d) sh[tid] += sh[tid + d];
        __syncthreads();
    }
    if (tid == 0) g_part[blockIdx.x] = sh[0];
}

__global__ void scan_top_kernel(int nb, int n) {
    __shared__ int sh[MAX_PART];
    int tid = threadIdx.x;
    int v = (tid < nb) ? g_part[tid] : 0;
    sh[tid] = v;
    __syncthreads();
    for (int d = 1; d < MAX_PART; d <<= 1) {
        int t = (tid >= d) ? sh[tid - d] : 0;
        __syncthreads();
        sh[tid] += t;
        __syncthreads();
    }
    if (tid < nb) g_partoff[tid] = sh[tid] - v;
    if (tid == 0) g_off[n] = sh[nb - 1];
}

__global__ void __launch_bounds__(SCAN_BLK)
scan_emit_kernel(int n) {
    __shared__ int sh[SCAN_BLK];
    int tid = threadIdx.x;
    int i = blockIdx.x * SCAN_BLK + tid;
    unsigned long long pk = (i < n) ? g_pack[i] : 0ULL;
    int dg = (int)(pk >> 40);
    sh[tid] = dg;
    __syncthreads();
    for (int d = 1; d < SCAN_BLK; d <<= 1) {
        int t = (tid >= d) ? sh[tid - d] : 0;
        __syncthreads();
        sh[tid] += t;
        __syncthreads();
    }
    if (i < n) {
        int ex = sh[tid] - dg + g_partoff[blockIdx.x];
        g_off[i]    = ex;
        g_cursor[i] = ex;
        float sw = (float)(pk & ((1ULL << 40) - 1ULL)) * (1.0f / 1048576.f);
        float dgf = (float)dg;
        float smv = 0.f, shv = 0.f;
        if (dg > 0) {
            float inv = 1.0f / (dgf + 1.0f);
            shv = inv;
            float swp = (sw == 0.f) ? 1.f : sw;
            smv = dgf * inv / swp;
        }
        g_scales[i]     = smv;
        g_scales[n + i] = shv;
    }
}

__global__ void scatter_kernel(const int* __restrict__ src,
                               const int* __restrict__ dst,
                               const float* __restrict__ w, int E) {
    int e = blockIdx.x * blockDim.x + threadIdx.x;
    if (e >= E) return;
    int d = dst[e];
    int pos = atomicAdd(&g_cursor[d], 1);
    g_epack[pos] = make_int2(src[e], __float_as_int(w[e]));
}

// fp32 -> fp16 table convert (features, once)
__global__ void convert_f16_kernel(const float4* __restrict__ h, int n4) {
    int i = blockIdx.x * blockDim.x + threadIdx.x;
    if (i >= n4) return;
    float4 v = h[i];
    __half2 p0 = __float22half2_rn(make_float2(v.x, v.y));
    __half2 p1 = __float22half2_rn(make_float2(v.z, v.w));
    uint2 u;
    u.x = *reinterpret_cast<uint32_t*>(&p0);
    u.y = *reinterpret_cast<uint32_t*>(&p1);
    g_hf16[i] = u;
}

// Warp-per-node CSR aggregate. Messages gathered from the fp16 table
// (halved traffic), self term + accumulation in fp32.
__global__ void __launch_bounds__(256)
agg_csr_kernel(const float4* __restrict__ h, float4* __restrict__ X, int n) {
    int node = (blockIdx.x * blockDim.x + threadIdx.x) >> 5;
    int lane = threadIdx.x & 31;
    if (node >= n) return;
    int start = g_off[node];
    int end   = g_off[node + 1];
    float4 acc = make_float4(0.f, 0.f, 0.f, 0.f);
    const unsigned FULL = 0xffffffffu;
    int l8 = lane & 7;
    int idx0 = start + l8;
    int2 p = (idx0 < end) ? g_epack[idx0] : make_int2(0, 0);
    for (int base = start; base < end; base += 8) {
        int2 cur = p;
        int nidx = base + 8 + l8;
        p = (nidx < end) ? g_epack[nidx] : make_int2(0, 0);

        int   ss[8];
        float ww[8];
#pragma unroll
        for (int j = 0; j < 8; j++) {
            ss[j] = __shfl_sync(FULL, cur.x, j);
            ww[j] = __int_as_float(__shfl_sync(FULL, cur.y, j));
        }
        uint2 v[8];
#pragma unroll
        for (int j = 0; j < 8; j++)
            v[j] = (base + j < end) ? g_hf16[ss[j] * 32 + lane]
                                    : make_uint2(0u, 0u);
#pragma unroll
        for (int j = 0; j < 8; j++) {
            float2 f01 = __half22float2(
                *reinterpret_cast<const __half2*>(&v[j].x));
            float2 f23 = __half22float2(
                *reinterpret_cast<const __half2*>(&v[j].y));
            acc.x = fmaf(f01.x, ww[j], acc.x);
            acc.y = fmaf(f01.y, ww[j], acc.y);
            acc.z = fmaf(f23.x, ww[j], acc.z);
            acc.w = fmaf(f23.y, ww[j], acc.w);
        }
    }
    float sm = g_scales[node];
    float sh = g_scales[n + node];
    float4 self = h[node * 32 + lane];   // fp32 self term
    float4 o;
    o.x = fmaf(sm, acc.x, sh * self.x);
    o.y = fmaf(sm, acc.y, sh * self.y);
    o.z = fmaf(sm, acc.z, sh * self.z);
    o.w = fmaf(sm, acc.w, sh * self.w);
    X[node * 32 + lane] = o;
}

// ---------------------------------------------------------------------------
// FFMA update, 8-node register blocking: hout = relu(X@W^T + b).
// Optionally also writes the fp16 gather copy for the next layer.
__global__ void __launch_bounds__(256)
update_kernel(const float4* __restrict__ X,
              const float* __restrict__ W,     // [128,128] row-major [o][k]
              const float* __restrict__ bias,
              float* __restrict__ hout,
              uint2* __restrict__ fout,        // fp16 copy or nullptr
              int n) {
    extern __shared__ float smem[];
    float* Ws = smem;                 // 128 * 132
    float* Xs = smem + FDIM * WPITCH; // 64 * 128
    int tid = threadIdx.x;

    for (int i = tid; i < FDIM * FDIM; i += 256) {
        int o = i >> 7, k = i & 127;
        Ws[k * WPITCH + o] = W[i];
    }

    int lane = tid & 31;
    int wp   = tid >> 5;
    float4 bv = *reinterpret_cast<const float4*>(&bias[lane * 4]);

    int ntiles = n / TM;
    for (int tile = blockIdx.x; tile < ntiles; tile += gridDim.x) {
        __syncthreads();
        int n0 = tile * TM;
        float4* Xs4 = reinterpret_cast<float4*>(Xs);
        for (int i = tid; i < TM * 32; i += 256)
            Xs4[i] = X[n0 * 32 + i];
        __syncthreads();

        float acc[8][4];
#pragma unroll
        for (int j = 0; j < 8; j++) {
            acc[j][0] = bv.x; acc[j][1] = bv.y;
            acc[j][2] = bv.z; acc[j][3] = bv.w;
        }
#pragma unroll 2
        for (int k = 0; k < FDIM; k++) {
            float4 wv = *reinterpret_cast<const float4*>(&Ws[k * WPITCH + lane * 4]);
#pragma unroll
            for (int j = 0; j < 8; j++) {
                float xv = Xs[((wp << 3) + j) * FDIM + k];
                acc[j][0] = fmaf(xv, wv.x, acc[j][0]);
                acc[j][1] = fmaf(xv, wv.y, acc[j][1]);
                acc[j][2] = fmaf(xv, wv.z, acc[j][2]);
                acc[j][3] = fmaf(xv, wv.w, acc[j][3]);
            }
        }
#pragma unroll
        for (int j = 0; j < 8; j++) {
            int node = n0 + (wp << 3) + j;
            float4 r;
            r.x = fmaxf(acc[j][0], 0.f);
            r.y = fmaxf(acc[j][1], 0.f);
            r.z = fmaxf(acc[j][2], 0.f);
            r.w = fmaxf(acc[j][3], 0.f);
            *reinterpret_cast<float4*>(&hout[node * FDIM + lane * 4]) = r;
            if (fout) {
                __half2 p0 = __float22half2_rn(make_float2(r.x, r.y));
                __half2 p1 = __float22half2_rn(make_float2(r.z, r.w));
                uint2 u;
                u.x = *reinterpret_cast<uint32_t*>(&p0);
                u.y = *reinterpret_cast<uint32_t*>(&p1);
                fout[node * 32 + lane] = u;
            }
        }
    }
}

// Final classifier: out = h2 @ Wo^T + bo
__global__ void __launch_bounds__(256)
out_kernel(const float4* __restrict__ h2,
           const float* __restrict__ Wo, const float* __restrict__ bo,
           float* __restrict__ out, int n) {
    __shared__ float Wos[FDIM * 32];
    int tid = threadIdx.x;
    for (int i = tid; i < 32 * FDIM; i += 256) {
        int o = i >> 7, k = i & 127;
        Wos[k * 32 + o] = Wo[i];
    }
    __syncthreads();

    int lane = tid & 31;
    int wp   = tid >> 5;
    float bias = bo[lane];
    for (int node = blockIdx.x * 8 + wp; node < n; node += gridDim.x * 8) {
        float4 x = h2[node * 32 + lane];
        float acc = bias;
#pragma unroll
        for (int j = 0; j < 32; j++) {
            float a = __shfl_sync(0xffffffffu, x.x, j);
            float b = __shfl_sync(0xffffffffu, x.y, j);
            float c = __shfl_sync(0xffffffffu, x.z, j);
            float d = __shfl_sync(0xffffffffu, x.w, j);
            int k = j << 2;
            acc += a * Wos[(k + 0) * 32 + lane];
            acc += b * Wos[(k + 1) * 32 + lane];
            acc += c * Wos[(k + 2) * 32 + lane];
            acc += d * Wos[(k + 3) * 32 + lane];
        }
        out[node * 32 + lane] = acc;
    }
}

// ---------------------------------------------------------------------------
extern "C" void kernel_launch(void* const* d_in, const int* in_sizes, int n_in,
                              void* d_out, int out_size) {
    const float* features = (const float*)d_in[0];
    const int*   src      = (const int*)  d_in[1];
    const int*   dst      = (const int*)  d_in[2];
    const float* weight   = (const float*)d_in[3];
    const float* W1       = (const float*)d_in[4];
    const float* b1       = (const float*)d_in[5];
    const float* W2       = (const float*)d_in[6];
    const float* b2       = (const float*)d_in[7];
    const float* Wo       = (const float*)d_in[8];
    const float* bo       = (const float*)d_in[9];
    float* out = (float*)d_out;

    int N = in_sizes[0] / FDIM;
    int E = in_sizes[1];

    void *pX_v, *ph1_v, *ph2_v, *ppack_v, *phf_v;
    cudaGetSymbolAddress(&pX_v,  g_X);
    cudaGetSymbolAddress(&ph1_v, g_h1);
    cudaGetSymbolAddress(&ph2_v, g_h2);
    cudaGetSymbolAddress(&ppack_v, g_pack);
    cudaGetSymbolAddress(&phf_v, g_hf16);
    float* pX  = (float*)pX_v;
    float* ph1 = (float*)ph1_v;
    float* ph2 = (float*)ph2_v;
    uint2* phf = (uint2*)phf_v;

    const int smem_bytes = (FDIM * WPITCH + TM * FDIM) * (int)sizeof(float);
    cudaFuncSetAttribute(update_kernel,
                         cudaFuncAttributeMaxDynamicSharedMemorySize, smem_bytes);

    int nb = (N + SCAN_BLK - 1) / SCAN_BLK;

    // CSR build (shared by both layers) + feature fp16 table
    cudaMemsetAsync(ppack_v, 0, N * sizeof(unsigned long long));
    edge_stats_kernel<<<(E + 255) / 256, 256>>>(dst, weight, E);
    scan_partial_kernel<<<nb, SCAN_BLK>>>(N);
    scan_top_kernel<<<1, MAX_PART>>>(nb, N);
    scan_emit_kernel<<<nb, SCAN_BLK>>>(N);
    scatter_kernel<<<(E + 255) / 256, 256>>>(src, dst, weight, E);
    convert_f16_kernel<<<(N * 32 + 255) / 256, 256>>>((const float4*)features, N * 32);

    int agg_grid = (N * 32 + 255) / 256;
    int upd_grid = 313;   // 625 tiles -> every block <= 2 tiles

    // Layer 1 (update also emits fp16 copy of h1 for layer-2 gathers)
    agg_csr_kernel<<<agg_grid, 256>>>((const float4*)features, (float4*)pX, N);
    update_kernel<<<upd_grid, 256, smem_bytes>>>((const float4*)pX, W1, b1, ph1, phf, N);

    // Layer 2
    agg_csr_kernel<<<agg_grid, 256>>>((const float4*)ph1, (float4*)pX, N);
    update_kernel<<<upd_grid, 256, smem_bytes>>>((const float4*)pX, W2, b2, ph2, nullptr, N);

    // Classifier
    out_kernel<<<2048, 256>>>((const float4*)ph2, Wo, bo, out, N);
}

// round 11
// speedup vs baseline: 1.4453x; 1.4182x over previous
#include <cuda_runtime.h>
#include <cuda_fp16.h>
#include <cstdint>

#define MAXN 40000
#define MAXE 1048576
#define FDIM 128
#define SCAN_BLK 1024
#define MAX_PART 64
#define XPITCH 68     // words, X tile pitch (bank-distinct A frags)
#define WPITCH16 136  // words, W tile pitch (bank-distinct B frags)

// Static scratch (no allocation allowed)
__device__ unsigned long long g_pack[MAXN];  // deg<<40 | sumw*2^20
__device__ float g_scales [2 * MAXN];        // [0,N): sm   [N,2N): sh
__device__ int   g_off    [MAXN + 1];
__device__ int   g_cursor [MAXN];
__device__ int   g_part   [MAX_PART];
__device__ int   g_partoff[MAX_PART];
__device__ int2  g_epack  [MAXE];            // .x = src, .y = float bits of w
__device__ uint2 g_Xf [MAXN * (FDIM / 4)];   // X in fp16 (half2 pairs)
__device__ float g_h1 [MAXN * FDIM];
__device__ float g_h2 [MAXN * FDIM];

// ---------------------------------------------------------------------------
__global__ void edge_stats_kernel(const int* __restrict__ dst,
                                  const float* __restrict__ w, int E) {
    int e = blockIdx.x * blockDim.x + threadIdx.x;
    if (e >= E) return;
    unsigned long long add =
        (1ULL << 40) | (unsigned long long)__float2uint_rn(w[e] * 1048576.f);
    atomicAdd(&g_pack[dst[e]], add);
}

__global__ void __launch_bounds__(SCAN_BLK)
scan_partial_kernel(int n) {
    __shared__ int sh[SCAN_BLK];
    int tid = threadIdx.x;
    int i = blockIdx.x * SCAN_BLK + tid;
    sh[tid] = (i < n) ? (int)(g_pack[i] >> 40) : 0;
    __syncthreads();
    for (int d = SCAN_BLK / 2; d > 0; d >>= 1) {
        if (tid < d) sh[tid] += sh[tid + d];
        __syncthreads();
    }
    if (tid == 0) g_part[blockIdx.x] = sh[0];
}

__global__ void scan_top_kernel(int nb, int n) {
    __shared__ int sh[MAX_PART];
    int tid = threadIdx.x;
    int v = (tid < nb) ? g_part[tid] : 0;
    sh[tid] = v;
    __syncthreads();
    for (int d = 1; d < MAX_PART; d <<= 1) {
        int t = (tid >= d) ? sh[tid - d] : 0;
        __syncthreads();
        sh[tid] += t;
        __syncthreads();
    }
    if (tid < nb) g_partoff[tid] = sh[tid] - v;
    if (tid == 0) g_off[n] = sh[nb - 1];
}

__global__ void __launch_bounds__(SCAN_BLK)
scan_emit_kernel(int n) {
    __shared__ int sh[SCAN_BLK];
    int tid = threadIdx.x;
    int i = blockIdx.x * SCAN_BLK + tid;
    unsigned long long pk = (i < n) ? g_pack[i] : 0ULL;
    int dg = (int)(pk >> 40);
    sh[tid] = dg;
    __syncthreads();
    for (int d = 1; d < SCAN_BLK; d <<= 1) {
        int t = (tid >= d) ? sh[tid - d] : 0;
        __syncthreads();
        sh[tid] += t;
        __syncthreads();
    }
    if (i < n) {
        int ex = sh[tid] - dg + g_partoff[blockIdx.x];
        g_off[i]    = ex;
        g_cursor[i] = ex;
        float sw = (float)(pk & ((1ULL << 40) - 1ULL)) * (1.0f / 1048576.f);
        float dgf = (float)dg;
        float smv = 0.f, shv = 0.f;
        if (dg > 0) {
            float inv = 1.0f / (dgf + 1.0f);
            shv = inv;
            float swp = (sw == 0.f) ? 1.f : sw;
            smv = dgf * inv / swp;
        }
        g_scales[i]     = smv;
        g_scales[n + i] = shv;
    }
}

__global__ void scatter_kernel(const int* __restrict__ src,
                               const int* __restrict__ dst,
                               const float* __restrict__ w, int E) {
    int e = blockIdx.x * blockDim.x + threadIdx.x;
    if (e >= E) return;
    int d = dst[e];
    int pos = atomicAdd(&g_cursor[d], 1);
    g_epack[pos] = make_int2(src[e], __float_as_int(w[e]));
}

// Warp-per-node CSR aggregate (R7-proven fp32 gathers); X emitted in fp16.
__global__ void __launch_bounds__(256)
agg_csr_kernel(const float4* __restrict__ h, uint2* __restrict__ Xf, int n) {
    int node = (blockIdx.x * blockDim.x + threadIdx.x) >> 5;
    int lane = threadIdx.x & 31;
    if (node >= n) return;
    int start = g_off[node];
    int end   = g_off[node + 1];
    float4 acc = make_float4(0.f, 0.f, 0.f, 0.f);
    const unsigned FULL = 0xffffffffu;
    int l8 = lane & 7;
    int idx0 = start + l8;
    int2 p = (idx0 < end) ? g_epack[idx0] : make_int2(0, 0);
    for (int base = start; base < end; base += 8) {
        int2 cur = p;
        int nidx = base + 8 + l8;
        p = (nidx < end) ? g_epack[nidx] : make_int2(0, 0);

        int   ss[8];
        float ww[8];
#pragma unroll
        for (int j = 0; j < 8; j++) {
            ss[j] = __shfl_sync(FULL, cur.x, j);
            ww[j] = __int_as_float(__shfl_sync(FULL, cur.y, j));
        }
        float4 v[8];
#pragma unroll
        for (int j = 0; j < 8; j++)
            v[j] = (base + j < end) ? h[ss[j] * 32 + lane]
                                    : make_float4(0.f, 0.f, 0.f, 0.f);
#pragma unroll
        for (int j = 0; j < 8; j++) {
            acc.x = fmaf(v[j].x, ww[j], acc.x);
            acc.y = fmaf(v[j].y, ww[j], acc.y);
            acc.z = fmaf(v[j].z, ww[j], acc.z);
            acc.w = fmaf(v[j].w, ww[j], acc.w);
        }
    }
    float sm = g_scales[node];
    float sh = g_scales[n + node];
    float4 self = h[node * 32 + lane];
    float ox = fmaf(sm, acc.x, sh * self.x);
    float oy = fmaf(sm, acc.y, sh * self.y);
    float oz = fmaf(sm, acc.z, sh * self.z);
    float ow = fmaf(sm, acc.w, sh * self.w);
    __half2 p01 = __floats2half2_rn(ox, oy);
    __half2 p23 = __floats2half2_rn(oz, ow);
    uint2 u;
    u.x = *reinterpret_cast<uint32_t*>(&p01);
    u.y = *reinterpret_cast<uint32_t*>(&p23);
    Xf[node * 32 + lane] = u;
}

// ---------------------------------------------------------------------------
// fp16 tensor-core update: hout = relu(X @ W^T + b).
// X single fp16 (pre-packed by agg), W split Whi+Wlo fp16 (2 passes -> fp32 W).
// Tile 64 nodes x 128 outs; 8 warps, each m32 x n32 via m16n8k16 mma.

__device__ __forceinline__ void mma_f16(float acc[4], const uint32_t a[4],
                                        uint32_t b0, uint32_t b1) {
    asm volatile(
        "mma.sync.aligned.m16n8k16.row.col.f32.f16.f16.f32 "
        "{%0,%1,%2,%3}, {%4,%5,%6,%7}, {%8,%9}, {%0,%1,%2,%3};"
        : "+f"(acc[0]), "+f"(acc[1]), "+f"(acc[2]), "+f"(acc[3])
        : "r"(a[0]), "r"(a[1]), "r"(a[2]), "r"(a[3]), "r"(b0), "r"(b1));
}

__global__ void __launch_bounds__(256)
update_kernel(const uint2* __restrict__ X,   // [N][32] half2-pairs
              const float* __restrict__ W,   // [128,128] row-major [o][k]
              const float* __restrict__ bias,
              float* __restrict__ hout, int n) {
    extern __shared__ uint32_t smw[];
    uint32_t* Whi = smw;                       // 64 * 136
    uint32_t* Wlo = smw + 64 * WPITCH16;       // 64 * 136
    uint32_t* Xs  = smw + 2 * 64 * WPITCH16;   // 64 * 68
    int tid = threadIdx.x;

    // W -> fp16 hi/lo, packed as half2 over k-pairs, layout [kpair][o]
    for (int i = tid; i < 64 * 128; i += 256) {
        int o = i >> 6, kp = i & 63;
        float2 w2 = reinterpret_cast<const float2*>(W)[o * 64 + kp];
        __half hx = __float2half_rn(w2.x);
        __half hy = __float2half_rn(w2.y);
        __half lx = __float2half_rn(w2.x - __half2float(hx));
        __half ly = __float2half_rn(w2.y - __half2float(hy));
        __half2 hh = __halves2half2(hx, hy);
        __half2 ll = __halves2half2(lx, ly);
        Whi[kp * WPITCH16 + o] = *reinterpret_cast<uint32_t*>(&hh);
        Wlo[kp * WPITCH16 + o] = *reinterpret_cast<uint32_t*>(&ll);
    }

    int lane = tid & 31, warp = tid >> 5;
    int grp = lane >> 2, tig = lane & 3;
    int wm = warp >> 2, wn = warp & 3;       // wm 0..1, wn 0..3
    int rm = wm * 32 + grp;
    int cw = wn * 32 + grp;

    int ntiles = (n + 63) >> 6;
    for (int tile = blockIdx.x; tile < ntiles; tile += gridDim.x) {
        __syncthreads();
        int n0 = tile << 6;
        // Load X tile (64 rows x 32 uint2) into smem, pitch 68 words
        for (int i = tid; i < 64 * 32; i += 256) {
            int row = i >> 5, l = i & 31;
            uint2 v = make_uint2(0u, 0u);
            if (n0 + row < n) v = X[(n0 + row) * 32 + l];
            *reinterpret_cast<uint2*>(&Xs[row * XPITCH + l * 2]) = v;
        }
        __syncthreads();

        float acc[2][4][4];
#pragma unroll
        for (int nb = 0; nb < 4; nb++) {
            int c = wn * 32 + nb * 8 + 2 * tig;
            float b0 = bias[c], b1 = bias[c + 1];
#pragma unroll
            for (int mb = 0; mb < 2; mb++) {
                acc[mb][nb][0] = b0; acc[mb][nb][1] = b1;
                acc[mb][nb][2] = b0; acc[mb][nb][3] = b1;
            }
        }

#pragma unroll
        for (int k0 = 0; k0 < 128; k0 += 16) {
            int p0 = (k0 >> 1) + tig;
            uint32_t a[2][4];
#pragma unroll
            for (int mb = 0; mb < 2; mb++) {
                int r0 = rm + mb * 16;
                a[mb][0] = Xs[r0 * XPITCH + p0];
                a[mb][1] = Xs[(r0 + 8) * XPITCH + p0];
                a[mb][2] = Xs[r0 * XPITCH + p0 + 4];
                a[mb][3] = Xs[(r0 + 8) * XPITCH + p0 + 4];
            }
#pragma unroll
            for (int pass = 0; pass < 2; pass++) {
                uint32_t* Wp = pass ? Wlo : Whi;
#pragma unroll
                for (int nb = 0; nb < 4; nb++) {
                    uint32_t b0 = Wp[p0 * WPITCH16 + cw + nb * 8];
                    uint32_t b1 = Wp[(p0 + 4) * WPITCH16 + cw + nb * 8];
#pragma unroll
                    for (int mb = 0; mb < 2; mb++)
                        mma_f16(acc[mb][nb], a[mb], b0, b1);
                }
            }
        }

        // Epilogue: relu + fp32 store (R2-verified m16n8 mapping)
#pragma unroll
        for (int mb = 0; mb < 2; mb++) {
            int r0 = n0 + wm * 32 + mb * 16 + grp;
            int r1 = r0 + 8;
#pragma unroll
            for (int nb = 0; nb < 4; nb++) {
                int c = wn * 32 + nb * 8 + 2 * tig;
                if (r0 < n) {
                    float2 v0 = make_float2(fmaxf(acc[mb][nb][0], 0.f),
                                            fmaxf(acc[mb][nb][1], 0.f));
                    *reinterpret_cast<float2*>(&hout[r0 * FDIM + c]) = v0;
                }
                if (r1 < n) {
                    float2 v1 = make_float2(fmaxf(acc[mb][nb][2], 0.f),
                                            fmaxf(acc[mb][nb][3], 0.f));
                    *reinterpret_cast<float2*>(&hout[r1 * FDIM + c]) = v1;
                }
            }
        }
    }
}

// Final classifier: out = h2 @ Wo^T + bo
__global__ void __launch_bounds__(256)
out_kernel(const float4* __restrict__ h2,
           const float* __restrict__ Wo, const float* __restrict__ bo,
           float* __restrict__ out, int n) {
    __shared__ float Wos[FDIM * 32];
    int tid = threadIdx.x;
    for (int i = tid; i < 32 * FDIM; i += 256) {
        int o = i >> 7, k = i & 127;
        Wos[k * 32 + o] = Wo[i];
    }
    __syncthreads();

    int lane = tid & 31;
    int wp   = tid >> 5;
    float bias = bo[lane];
    for (int node = blockIdx.x * 8 + wp; node < n; node += gridDim.x * 8) {
        float4 x = h2[node * 32 + lane];
        float acc = bias;
#pragma unroll
        for (int j = 0; j < 32; j++) {
            float a = __shfl_sync(0xffffffffu, x.x, j);
            float b = __shfl_sync(0xffffffffu, x.y, j);
            float c = __shfl_sync(0xffffffffu, x.z, j);
            float d = __shfl_sync(0xffffffffu, x.w, j);
            int k = j << 2;
            acc += a * Wos[(k + 0) * 32 + lane];
            acc += b * Wos[(k + 1) * 32 + lane];
            acc += c * Wos[(k + 2) * 32 + lane];
            acc += d * Wos[(k + 3) * 32 + lane];
        }
        out[node * 32 + lane] = acc;
    }
}

// ---------------------------------------------------------------------------
extern "C" void kernel_launch(void* const* d_in, const int* in_sizes, int n_in,
                              void* d_out, int out_size) {
    const float* features = (const float*)d_in[0];
    const int*   src      = (const int*)  d_in[1];
    const int*   dst      = (const int*)  d_in[2];
    const float* weight   = (const float*)d_in[3];
    const float* W1       = (const float*)d_in[4];
    const float* b1       = (const float*)d_in[5];
    const float* W2       = (const float*)d_in[6];
    const float* b2       = (const float*)d_in[7];
    const float* Wo       = (const float*)d_in[8];
    const float* bo       = (const float*)d_in[9];
    float* out = (float*)d_out;

    int N = in_sizes[0] / FDIM;
    int E = in_sizes[1];

    void *pXf_v, *ph1_v, *ph2_v, *ppack_v;
    cudaGetSymbolAddress(&pXf_v, g_Xf);
    cudaGetSymbolAddress(&ph1_v, g_h1);
    cudaGetSymbolAddress(&ph2_v, g_h2);
    cudaGetSymbolAddress(&ppack_v, g_pack);
    uint2* pXf = (uint2*)pXf_v;
    float* ph1 = (float*)ph1_v;
    float* ph2 = (float*)ph2_v;

    const int smem_bytes = (2 * 64 * WPITCH16 + 64 * XPITCH) * 4;  // 87040
    cudaFuncSetAttribute(update_kernel,
                         cudaFuncAttributeMaxDynamicSharedMemorySize, smem_bytes);

    int nb = (N + SCAN_BLK - 1) / SCAN_BLK;

    // CSR build (shared by both layers)
    cudaMemsetAsync(ppack_v, 0, N * sizeof(unsigned long long));
    edge_stats_kernel<<<(E + 255) / 256, 256>>>(dst, weight, E);
    scan_partial_kernel<<<nb, SCAN_BLK>>>(N);
    scan_top_kernel<<<1, MAX_PART>>>(nb, N);
    scan_emit_kernel<<<nb, SCAN_BLK>>>(N);
    scatter_kernel<<<(E + 255) / 256, 256>>>(src, dst, weight, E);

    int agg_grid = (N * 32 + 255) / 256;
    int upd_grid = 296;   // 2 blocks/SM

    // Layer 1
    agg_csr_kernel<<<agg_grid, 256>>>((const float4*)features, pXf, N);
    update_kernel<<<upd_grid, 256, smem_bytes>>>(pXf, W1, b1, ph1, N);

    // Layer 2
    agg_csr_kernel<<<agg_grid, 256>>>((const float4*)ph1, pXf, N);
    update_kernel<<<upd_grid, 256, smem_bytes>>>(pXf, W2, b2, ph2, N);

    // Classifier
    out_kernel<<<2048, 256>>>((const float4*)ph2, Wo, bo, out, N);
}